// round 11
// baseline (speedup 1.0000x reference)
#include <cuda_runtime.h>
#include <cuda_fp16.h>
#include <mma.h>
#include <cstdint>

using namespace nvcuda;

#define IN_FEAT   64
#define OUT_FEAT  64
#define MAX_NODES 100000
#define MAX_EDGES 1600000
#define NB_SCAN   ((MAX_NODES + 255) / 256)   // 391
#define CHUNK     128                          // edges per warp in accum

#define SA_LD 72
#define SC_LD 68

// Scratch (__device__ globals: allocation-free, zero-initialized at load)
__device__ __half2      g_h16[MAX_NODES * 32];   // h in fp16 (12.8 MB)
__device__ int          g_cnt[MAX_NODES];        // histogram (zero-invariant)
__device__ int          g_off[MAX_NODES + 1];    // CSR offsets
__device__ int          g_rank[MAX_EDGES];       // per-edge rank within its dst
__device__ unsigned int g_state[NB_SCAN];        // lookback: (flag<<30)|value
__device__ int2         g_pair[MAX_EDGES];       // dst-sorted (src, att)

// ---------------------------------------------------------------------------
// Kernel 1: h = feat @ W + b -> fp16, via HMMA (wmma 16x16x16, fp32 accum).
// ---------------------------------------------------------------------------
__global__ __launch_bounds__(256) void gemm_kernel(
    const float* __restrict__ feat,
    const float* __restrict__ W,
    const float* __restrict__ bias,
    __half2* __restrict__ h16,
    int n_nodes)
{
    extern __shared__ char smem[];
    __half (*sA)[SA_LD] = reinterpret_cast<__half(*)[SA_LD]>(smem);
    __half (*sB)[SA_LD] = reinterpret_cast<__half(*)[SA_LD]>(smem + 128 * SA_LD * 2);
    float*  sBias       = reinterpret_cast<float*>(smem + (128 + 64) * SA_LD * 2);
    float (*sC)[16][SC_LD] =
        reinterpret_cast<float(*)[16][SC_LD]>(smem + (128 + 64) * SA_LD * 2 + 256);

    const int tid  = threadIdx.x;
    const int row0 = blockIdx.x * 128;

    {
        int k = tid >> 2, c4 = tid & 3;
        const float4* ws = reinterpret_cast<const float4*>(W + k * OUT_FEAT + c4 * 16);
#pragma unroll
        for (int i = 0; i < 4; i++) {
            float4 v = ws[i];
            int c = c4 * 16 + i * 4;
            sB[k][c + 0] = __float2half(v.x); sB[k][c + 1] = __float2half(v.y);
            sB[k][c + 2] = __float2half(v.z); sB[k][c + 3] = __float2half(v.w);
        }
    }
    if (tid < OUT_FEAT) sBias[tid] = bias[tid];

    {
        int rl = tid >> 1, hf = tid & 1;
        int grow = row0 + rl;
        const float* fr = feat + (size_t)grow * IN_FEAT + hf * 32;
#pragma unroll
        for (int i = 0; i < 8; i++) {
            float4 v = (grow < n_nodes)
                ? *reinterpret_cast<const float4*>(fr + i * 4)
                : make_float4(0.f, 0.f, 0.f, 0.f);
            int c = hf * 32 + i * 4;
            sA[rl][c + 0] = __float2half(v.x); sA[rl][c + 1] = __float2half(v.y);
            sA[rl][c + 2] = __float2half(v.z); sA[rl][c + 3] = __float2half(v.w);
        }
    }
    __syncthreads();

    const int w    = tid >> 5;
    const int lane = tid & 31;

    wmma::fragment<wmma::accumulator, 16, 16, 16, float> c[4];
#pragma unroll
    for (int n = 0; n < 4; n++) wmma::fill_fragment(c[n], 0.0f);

#pragma unroll
    for (int k = 0; k < 4; k++) {
        wmma::fragment<wmma::matrix_a, 16, 16, 16, __half, wmma::row_major> a;
        wmma::load_matrix_sync(a, &sA[w * 16][k * 16], SA_LD);
#pragma unroll
        for (int n = 0; n < 4; n++) {
            wmma::fragment<wmma::matrix_b, 16, 16, 16, __half, wmma::row_major> b;
            wmma::load_matrix_sync(b, &sB[k * 16][n * 16], SA_LD);
            wmma::mma_sync(c[n], a, b, c[n]);
        }
    }
#pragma unroll
    for (int n = 0; n < 4; n++)
        wmma::store_matrix_sync(&sC[w][0][n * 16], c[n], SC_LD, wmma::mem_row_major);
    __syncwarp();

    int rr = lane >> 1, hf = lane & 1;
    int grow = row0 + w * 16 + rr;
    if (grow < n_nodes) {
#pragma unroll
        for (int i = 0; i < 8; i++) {
            int col = hf * 32 + i * 4;
            float x0 = sC[w][rr][col + 0] + sBias[col + 0];
            float x1 = sC[w][rr][col + 1] + sBias[col + 1];
            float x2 = sC[w][rr][col + 2] + sBias[col + 2];
            float x3 = sC[w][rr][col + 3] + sBias[col + 3];
            __half2 p0 = __floats2half2_rn(x0, x1);
            __half2 p1 = __floats2half2_rn(x2, x3);
            uint2 u;
            u.x = *reinterpret_cast<uint32_t*>(&p0);
            u.y = *reinterpret_cast<uint32_t*>(&p1);
            *reinterpret_cast<uint2*>(h16 + (size_t)grow * 32 + col / 2) = u;
        }
    }
}

#define GEMM_SMEM ((128 + 64) * SA_LD * 2 + 256 + 8 * 16 * SC_LD * 4)

// ---------------------------------------------------------------------------
// zero_out: out poisoned to 0xAA; accum relies on zeros (RED + skipped nodes)
// ---------------------------------------------------------------------------
__global__ void zero_kernel(float4* __restrict__ out, int n4)
{
    int i = blockIdx.x * blockDim.x + threadIdx.x;
    if (i < n4) out[i] = make_float4(0.f, 0.f, 0.f, 0.f);
}

// ---------------------------------------------------------------------------
// hist: 4 edges/thread (int4), rank = atomicAdd return. Block 0 zeroes
// lookback state. g_cnt zero on entry — invariant.
// ---------------------------------------------------------------------------
__global__ void hist_kernel(const int* __restrict__ dst, int n_edges)
{
    if (blockIdx.x == 0)
        for (int i = threadIdx.x; i < NB_SCAN; i += blockDim.x) g_state[i] = 0u;
    int e = (blockIdx.x * blockDim.x + threadIdx.x) * 4;
    if (e + 3 < n_edges) {
        int4 d = *reinterpret_cast<const int4*>(dst + e);
        int4 r;
        r.x = atomicAdd(&g_cnt[d.x], 1);
        r.y = atomicAdd(&g_cnt[d.y], 1);
        r.z = atomicAdd(&g_cnt[d.z], 1);
        r.w = atomicAdd(&g_cnt[d.w], 1);
        *reinterpret_cast<int4*>(g_rank + e) = r;
    } else {
        for (; e < n_edges; e++)
            g_rank[e] = atomicAdd(&g_cnt[dst[e]], 1);
    }
}

// ---------------------------------------------------------------------------
// scan: single-pass decoupled lookback, warp-parallel window.
// ---------------------------------------------------------------------------
__global__ __launch_bounds__(256) void scan_kernel(int n, int n_edges)
{
    __shared__ int wsum[8];
    __shared__ int sPrefix;

    int b    = blockIdx.x;
    int i    = b * 256 + threadIdx.x;
    int lane = threadIdx.x & 31;
    int wid  = threadIdx.x >> 5;
    int v    = (i < n) ? g_cnt[i] : 0;
    if (i < n) g_cnt[i] = 0;              // restore zero-invariant

    int x = v;
#pragma unroll
    for (int off = 1; off < 32; off <<= 1) {
        int t = __shfl_up_sync(0xffffffff, x, off);
        if (lane >= off) x += t;
    }
    if (lane == 31) wsum[wid] = x;
    __syncthreads();
    if (wid == 0) {
        int s = (lane < 8) ? wsum[lane] : 0;
#pragma unroll
        for (int off = 1; off < 8; off <<= 1) {
            int t = __shfl_up_sync(0xffffffff, s, off);
            if (lane >= off) s += t;
        }
        if (lane < 8) wsum[lane] = s;
    }
    __syncthreads();
    int incl = x + (wid > 0 ? wsum[wid - 1] : 0);
    unsigned int agg = (unsigned int)wsum[7];

    if (wid == 0) {
        volatile unsigned int* st = g_state;
        if (b == 0) {
            if (lane == 0) { st[0] = (2u << 30) | agg; sPrefix = 0; }
        } else {
            if (lane == 0) st[b] = (1u << 30) | agg;
            __syncwarp();
            unsigned int run = 0u;
            int idx = b - 1;
            while (true) {
                int my = idx - lane;
                unsigned int s;
                do {
                    s = (my >= 0) ? st[my] : ((1u << 30) | 0u);
                } while ((s >> 30) == 0u);
                unsigned int ball = __ballot_sync(0xffffffff, (s >> 30) == 2u);
                unsigned int val  = s & 0x3FFFFFFFu;
                if (ball) {
                    int lead = __ffs(ball) - 1;
                    unsigned int contrib = (lane <= lead) ? val : 0u;
#pragma unroll
                    for (int o = 16; o > 0; o >>= 1)
                        contrib += __shfl_down_sync(0xffffffff, contrib, o);
                    run += __shfl_sync(0xffffffff, contrib, 0);
                    break;
                } else {
                    unsigned int contrib = (my >= 0) ? val : 0u;
#pragma unroll
                    for (int o = 16; o > 0; o >>= 1)
                        contrib += __shfl_down_sync(0xffffffff, contrib, o);
                    run += __shfl_sync(0xffffffff, contrib, 0);
                    idx -= 32;
                }
            }
            if (lane == 0) {
                st[b] = (2u << 30) | (run + agg);
                sPrefix = (int)run;
            }
        }
    }
    __syncthreads();
    int prefix = sPrefix;

    if (i < n) g_off[i] = incl - v + prefix;
    if (i == n - 1) g_off[n] = prefix + incl;
}

// ---------------------------------------------------------------------------
// perm: atomic-free placement, 4 edges/thread for MLP.
// ---------------------------------------------------------------------------
__global__ void perm_kernel(const int* __restrict__ src,
                            const int* __restrict__ dst,
                            const float* __restrict__ att,
                            int n_edges)
{
    int e = (blockIdx.x * blockDim.x + threadIdx.x) * 4;
    if (e + 3 < n_edges) {
        int4   s = *reinterpret_cast<const int4*>(src + e);
        int4   d = *reinterpret_cast<const int4*>(dst + e);
        int4   r = *reinterpret_cast<const int4*>(g_rank + e);
        float4 a = *reinterpret_cast<const float4*>(att + e);
        int p0 = g_off[d.x] + r.x;
        int p1 = g_off[d.y] + r.y;
        int p2 = g_off[d.z] + r.z;
        int p3 = g_off[d.w] + r.w;
        g_pair[p0] = make_int2(s.x, __float_as_int(a.x));
        g_pair[p1] = make_int2(s.y, __float_as_int(a.y));
        g_pair[p2] = make_int2(s.z, __float_as_int(a.z));
        g_pair[p3] = make_int2(s.w, __float_as_int(a.w));
    } else {
        for (; e < n_edges; e++)
            g_pair[g_off[dst[e]] + g_rank[e]] = make_int2(src[e], __float_as_int(att[e]));
    }
}

// ---------------------------------------------------------------------------
// accum: EDGE-BALANCED. Warp owns CHUNK consecutive sorted edges; binary-
// search start node, walk segments. Fully-owned segment -> direct store;
// boundary segment -> red.global.add.v2.f32 onto zeroed out.
// Lane owns 2 cols (one half2 gather / float2 out).
// ---------------------------------------------------------------------------
__global__ __launch_bounds__(256) void accum_kernel(
    const __half2* __restrict__ h16,
    float* __restrict__ out,
    int n_nodes, int n_edges)
{
    int warp = (blockIdx.x * 256 + threadIdx.x) >> 5;
    int lane = threadIdx.x & 31;
    int e0 = warp * CHUNK;
    if (e0 >= n_edges) return;
    int e1 = min(e0 + CHUNK, n_edges);

    // binary search: largest node with off[node] <= e0 (uniform across warp)
    int lo = 0, hi = n_nodes - 1;
    while (lo < hi) {
        int mid = (lo + hi + 1) >> 1;
        if (__ldg(&g_off[mid]) <= e0) lo = mid; else hi = mid - 1;
    }
    int node = lo;
    int e = e0;

    while (e < e1) {
        int segStart = __ldg(&g_off[node]);
        int segEndG  = __ldg(&g_off[node + 1]);
        int segEnd   = min(segEndG, e1);

        float2 acc = make_float2(0.f, 0.f);
        int j = e;
        for (; j + 1 < segEnd; j += 2) {
            int2 p0 = __ldg(&g_pair[j]);
            int2 p1 = __ldg(&g_pair[j + 1]);
            float2 v0 = __half22float2(__ldg(h16 + (size_t)p0.x * 32 + lane));
            float2 v1 = __half22float2(__ldg(h16 + (size_t)p1.x * 32 + lane));
            float a0 = __int_as_float(p0.y), a1 = __int_as_float(p1.y);
            acc.x = fmaf(a0, v0.x, acc.x); acc.y = fmaf(a0, v0.y, acc.y);
            acc.x = fmaf(a1, v1.x, acc.x); acc.y = fmaf(a1, v1.y, acc.y);
        }
        if (j < segEnd) {
            int2 p = __ldg(&g_pair[j]);
            float a = __int_as_float(p.y);
            float2 v = __half22float2(__ldg(h16 + (size_t)p.x * 32 + lane));
            acc.x = fmaf(a, v.x, acc.x);
            acc.y = fmaf(a, v.y, acc.y);
        }

        float* o = out + (size_t)node * OUT_FEAT + lane * 2;
        bool full = (segStart >= e0) && (segEndG <= e1);
        if (full) {
            *reinterpret_cast<float2*>(o) = acc;
        } else {
            asm volatile("red.global.add.v2.f32 [%0], {%1, %2};"
                         :: "l"(o), "f"(acc.x), "f"(acc.y) : "memory");
        }
        e = segEnd;
        node++;
    }
}

// ---------------------------------------------------------------------------
// Launch: side stream = gemm + zero_out; main = hist -> scan -> perm; join.
// ---------------------------------------------------------------------------
extern "C" void kernel_launch(void* const* d_in, const int* in_sizes, int n_in,
                              void* d_out, int out_size)
{
    const float* feat = (const float*)d_in[0];
    const float* att  = (const float*)d_in[1];
    const int*   src  = (const int*)  d_in[2];
    const int*   dst  = (const int*)  d_in[3];
    const float* W    = (const float*)d_in[4];
    const float* bias = (const float*)d_in[5];
    float*       out  = (float*)d_out;

    int n_nodes = in_sizes[0] / IN_FEAT;
    int n_edges = in_sizes[2];

    __half2* h16;
    cudaGetSymbolAddress((void**)&h16, g_h16);

    cudaFuncSetAttribute(gemm_kernel,
                         cudaFuncAttributeMaxDynamicSharedMemorySize, GEMM_SMEM);

    cudaStream_t side;
    cudaStreamCreateWithFlags(&side, cudaStreamNonBlocking);
    cudaEvent_t evFork, evJoin;
    cudaEventCreateWithFlags(&evFork, cudaEventDisableTiming);
    cudaEventCreateWithFlags(&evJoin, cudaEventDisableTiming);

    // fork: gemm + zero_out on side stream
    cudaEventRecord(evFork, 0);
    cudaStreamWaitEvent(side, evFork, 0);
    gemm_kernel<<<(n_nodes + 127) / 128, 256, GEMM_SMEM, side>>>(feat, W, bias, h16, n_nodes);
    int n4 = out_size / 4;
    zero_kernel<<<(n4 + 255) / 256, 256, 0, side>>>((float4*)d_out, n4);
    cudaEventRecord(evJoin, side);

    // binning chain on main stream
    int vthreads = (n_edges + 3) / 4;
    hist_kernel<<<(vthreads + 255) / 256, 256>>>(dst, n_edges);
    scan_kernel<<<NB_SCAN, 256>>>(n_nodes, n_edges);
    perm_kernel<<<(vthreads + 255) / 256, 256>>>(src, dst, att, n_edges);

    // join, then edge-balanced accumulate
    cudaStreamWaitEvent(0, evJoin, 0);
    int n_chunks = (n_edges + CHUNK - 1) / CHUNK;
    accum_kernel<<<(n_chunks * 32 + 255) / 256, 256>>>(h16, out, n_nodes, n_edges);
}

// round 12
// speedup vs baseline: 1.2989x; 1.2989x over previous
#include <cuda_runtime.h>
#include <cuda_fp16.h>
#include <mma.h>
#include <cstdint>

using namespace nvcuda;

#define IN_FEAT   64
#define OUT_FEAT  64
#define MAX_NODES 100000
#define MAX_EDGES 1600000
#define NB_SCAN   ((MAX_NODES + 255) / 256)   // 391

#define SA_LD 72
#define SC_LD 68

// Scratch (__device__ globals: allocation-free, zero-initialized at load)
__device__ __half2 g_h16[MAX_NODES * 32];   // h in fp16 (12.8 MB)
__device__ int     g_cnt[MAX_NODES];        // histogram (zero-invariant)
__device__ int     g_off[MAX_NODES + 1];    // CSR offsets
__device__ int     g_rank[MAX_EDGES];       // per-edge rank within its dst
__device__ int     g_bsum[NB_SCAN];         // scan block sums
__device__ int2    g_pair[MAX_EDGES];       // dst-sorted (src, att)

// ---------------------------------------------------------------------------
// Kernel 1: h = feat @ W + b -> fp16, via HMMA (wmma 16x16x16, fp32 accum).
// ---------------------------------------------------------------------------
__global__ __launch_bounds__(256) void gemm_kernel(
    const float* __restrict__ feat,
    const float* __restrict__ W,
    const float* __restrict__ bias,
    __half2* __restrict__ h16,
    int n_nodes)
{
    extern __shared__ char smem[];
    __half (*sA)[SA_LD] = reinterpret_cast<__half(*)[SA_LD]>(smem);
    __half (*sB)[SA_LD] = reinterpret_cast<__half(*)[SA_LD]>(smem + 128 * SA_LD * 2);
    float*  sBias       = reinterpret_cast<float*>(smem + (128 + 64) * SA_LD * 2);
    float (*sC)[16][SC_LD] =
        reinterpret_cast<float(*)[16][SC_LD]>(smem + (128 + 64) * SA_LD * 2 + 256);

    const int tid  = threadIdx.x;
    const int row0 = blockIdx.x * 128;

    {
        int k = tid >> 2, c4 = tid & 3;
        const float4* ws = reinterpret_cast<const float4*>(W + k * OUT_FEAT + c4 * 16);
#pragma unroll
        for (int i = 0; i < 4; i++) {
            float4 v = ws[i];
            int c = c4 * 16 + i * 4;
            sB[k][c + 0] = __float2half(v.x); sB[k][c + 1] = __float2half(v.y);
            sB[k][c + 2] = __float2half(v.z); sB[k][c + 3] = __float2half(v.w);
        }
    }
    if (tid < OUT_FEAT) sBias[tid] = bias[tid];

    {
        int rl = tid >> 1, hf = tid & 1;
        int grow = row0 + rl;
        const float* fr = feat + (size_t)grow * IN_FEAT + hf * 32;
#pragma unroll
        for (int i = 0; i < 8; i++) {
            float4 v = (grow < n_nodes)
                ? *reinterpret_cast<const float4*>(fr + i * 4)
                : make_float4(0.f, 0.f, 0.f, 0.f);
            int c = hf * 32 + i * 4;
            sA[rl][c + 0] = __float2half(v.x); sA[rl][c + 1] = __float2half(v.y);
            sA[rl][c + 2] = __float2half(v.z); sA[rl][c + 3] = __float2half(v.w);
        }
    }
    __syncthreads();

    const int w    = tid >> 5;
    const int lane = tid & 31;

    wmma::fragment<wmma::accumulator, 16, 16, 16, float> c[4];
#pragma unroll
    for (int n = 0; n < 4; n++) wmma::fill_fragment(c[n], 0.0f);

#pragma unroll
    for (int k = 0; k < 4; k++) {
        wmma::fragment<wmma::matrix_a, 16, 16, 16, __half, wmma::row_major> a;
        wmma::load_matrix_sync(a, &sA[w * 16][k * 16], SA_LD);
#pragma unroll
        for (int n = 0; n < 4; n++) {
            wmma::fragment<wmma::matrix_b, 16, 16, 16, __half, wmma::row_major> b;
            wmma::load_matrix_sync(b, &sB[k * 16][n * 16], SA_LD);
            wmma::mma_sync(c[n], a, b, c[n]);
        }
    }
#pragma unroll
    for (int n = 0; n < 4; n++)
        wmma::store_matrix_sync(&sC[w][0][n * 16], c[n], SC_LD, wmma::mem_row_major);
    __syncwarp();

    int rr = lane >> 1, hf = lane & 1;
    int grow = row0 + w * 16 + rr;
    if (grow < n_nodes) {
#pragma unroll
        for (int i = 0; i < 8; i++) {
            int col = hf * 32 + i * 4;
            float x0 = sC[w][rr][col + 0] + sBias[col + 0];
            float x1 = sC[w][rr][col + 1] + sBias[col + 1];
            float x2 = sC[w][rr][col + 2] + sBias[col + 2];
            float x3 = sC[w][rr][col + 3] + sBias[col + 3];
            __half2 p0 = __floats2half2_rn(x0, x1);
            __half2 p1 = __floats2half2_rn(x2, x3);
            uint2 u;
            u.x = *reinterpret_cast<uint32_t*>(&p0);
            u.y = *reinterpret_cast<uint32_t*>(&p1);
            *reinterpret_cast<uint2*>(h16 + (size_t)grow * 32 + col / 2) = u;
        }
    }
}

#define GEMM_SMEM ((128 + 64) * SA_LD * 2 + 256 + 8 * 16 * SC_LD * 4)

// ---------------------------------------------------------------------------
// hist: 4 edges/thread (int4), rank = atomicAdd return value.
// g_cnt zero on entry — invariant (restored by scan1).
// ---------------------------------------------------------------------------
__global__ void hist_kernel(const int* __restrict__ dst, int n_edges)
{
    int e = (blockIdx.x * blockDim.x + threadIdx.x) * 4;
    if (e + 3 < n_edges) {
        int4 d = *reinterpret_cast<const int4*>(dst + e);
        int4 r;
        r.x = atomicAdd(&g_cnt[d.x], 1);
        r.y = atomicAdd(&g_cnt[d.y], 1);
        r.z = atomicAdd(&g_cnt[d.z], 1);
        r.w = atomicAdd(&g_cnt[d.w], 1);
        *reinterpret_cast<int4*>(g_rank + e) = r;
    } else {
        for (; e < n_edges; e++)
            g_rank[e] = atomicAdd(&g_cnt[dst[e]], 1);
    }
}

// ---------------------------------------------------------------------------
// scan1: per-block exclusive scan of g_cnt -> g_off (block-local),
//        block totals -> g_bsum, re-zero g_cnt (restores invariant).
// ---------------------------------------------------------------------------
__global__ __launch_bounds__(256) void scan1_kernel(int n)
{
    __shared__ int wsum[8];
    int i    = blockIdx.x * 256 + threadIdx.x;
    int lane = threadIdx.x & 31;
    int wid  = threadIdx.x >> 5;
    int v    = (i < n) ? g_cnt[i] : 0;
    if (i < n) g_cnt[i] = 0;

    int x = v;
#pragma unroll
    for (int off = 1; off < 32; off <<= 1) {
        int t = __shfl_up_sync(0xffffffff, x, off);
        if (lane >= off) x += t;
    }
    if (lane == 31) wsum[wid] = x;
    __syncthreads();
    if (wid == 0) {
        int s = (lane < 8) ? wsum[lane] : 0;
#pragma unroll
        for (int off = 1; off < 8; off <<= 1) {
            int t = __shfl_up_sync(0xffffffff, s, off);
            if (lane >= off) s += t;
        }
        if (lane < 8) wsum[lane] = s;
    }
    __syncthreads();
    int incl = x + (wid > 0 ? wsum[wid - 1] : 0);
    if (i < n) g_off[i] = incl - v;       // block-local exclusive
    if (threadIdx.x == 255) g_bsum[blockIdx.x] = incl;
}

// ---------------------------------------------------------------------------
// scan2b: each block redundantly reduces g_bsum[0..blockIdx) for its prefix,
//         applies global offset, writes g_off[n].
// ---------------------------------------------------------------------------
__global__ __launch_bounds__(256) void scan2b_kernel(int n, int n_edges)
{
    __shared__ int wred[8];
    int tid  = threadIdx.x;
    int lane = tid & 31;
    int wid  = tid >> 5;
    int b    = blockIdx.x;

    int local = 0;
    for (int t = tid; t < b; t += 256) local += g_bsum[t];
#pragma unroll
    for (int off = 16; off > 0; off >>= 1)
        local += __shfl_down_sync(0xffffffff, local, off);
    if (lane == 0) wred[wid] = local;
    __syncthreads();
    if (wid == 0) {
        int s = (lane < 8) ? wred[lane] : 0;
#pragma unroll
        for (int off = 4; off > 0; off >>= 1)
            s += __shfl_down_sync(0xffffffff, s, off);
        if (lane == 0) wred[0] = s;
    }
    __syncthreads();
    int prefix = wred[0];

    int i = b * 256 + tid;
    if (i < n) g_off[i] += prefix;
    if (b == 0 && tid == 0) g_off[n] = n_edges;
}

// ---------------------------------------------------------------------------
// perm: atomic-free placement (rank from hist), 4 edges/thread for MLP.
// ---------------------------------------------------------------------------
__global__ void perm_kernel(const int* __restrict__ src,
                            const int* __restrict__ dst,
                            const float* __restrict__ att,
                            int n_edges)
{
    int e = (blockIdx.x * blockDim.x + threadIdx.x) * 4;
    if (e + 3 < n_edges) {
        int4   s = *reinterpret_cast<const int4*>(src + e);
        int4   d = *reinterpret_cast<const int4*>(dst + e);
        int4   r = *reinterpret_cast<const int4*>(g_rank + e);
        float4 a = *reinterpret_cast<const float4*>(att + e);
        g_pair[g_off[d.x] + r.x] = make_int2(s.x, __float_as_int(a.x));
        g_pair[g_off[d.y] + r.y] = make_int2(s.y, __float_as_int(a.y));
        g_pair[g_off[d.z] + r.z] = make_int2(s.z, __float_as_int(a.z));
        g_pair[g_off[d.w] + r.w] = make_int2(s.w, __float_as_int(a.w));
    } else {
        for (; e < n_edges; e++)
            g_pair[g_off[dst[e]] + g_rank[e]] = make_int2(src[e], __float_as_int(att[e]));
    }
}

// ---------------------------------------------------------------------------
// accum: one warp per dst node; lane owns 2 cols; fp32 accumulation.
// Writes every node -> no zero pass needed.
// ---------------------------------------------------------------------------
__global__ __launch_bounds__(256) void accum_kernel(
    const __half2* __restrict__ h16,
    float* __restrict__ out,
    int n_nodes)
{
    int warp = (blockIdx.x * 256 + threadIdx.x) >> 5;
    int lane = threadIdx.x & 31;
    if (warp >= n_nodes) return;

    int j   = g_off[warp];
    int end = g_off[warp + 1];

    float2 acc = make_float2(0.f, 0.f);

    for (; j + 3 < end; j += 4) {
        int2 p0 = __ldg(&g_pair[j]);
        int2 p1 = __ldg(&g_pair[j + 1]);
        int2 p2 = __ldg(&g_pair[j + 2]);
        int2 p3 = __ldg(&g_pair[j + 3]);
        float2 v0 = __half22float2(__ldg(h16 + (size_t)p0.x * 32 + lane));
        float2 v1 = __half22float2(__ldg(h16 + (size_t)p1.x * 32 + lane));
        float2 v2 = __half22float2(__ldg(h16 + (size_t)p2.x * 32 + lane));
        float2 v3 = __half22float2(__ldg(h16 + (size_t)p3.x * 32 + lane));
        float a0 = __int_as_float(p0.y), a1 = __int_as_float(p1.y);
        float a2 = __int_as_float(p2.y), a3 = __int_as_float(p3.y);
        acc.x = fmaf(a0, v0.x, acc.x); acc.y = fmaf(a0, v0.y, acc.y);
        acc.x = fmaf(a1, v1.x, acc.x); acc.y = fmaf(a1, v1.y, acc.y);
        acc.x = fmaf(a2, v2.x, acc.x); acc.y = fmaf(a2, v2.y, acc.y);
        acc.x = fmaf(a3, v3.x, acc.x); acc.y = fmaf(a3, v3.y, acc.y);
    }
    for (; j < end; j++) {
        int2 p = __ldg(&g_pair[j]);
        float a = __int_as_float(p.y);
        float2 v = __half22float2(__ldg(h16 + (size_t)p.x * 32 + lane));
        acc.x = fmaf(a, v.x, acc.x);
        acc.y = fmaf(a, v.y, acc.y);
    }

    *reinterpret_cast<float2*>(out + (size_t)warp * OUT_FEAT + lane * 2) = acc;
}

// ---------------------------------------------------------------------------
// Launch: side stream = gemm; main = hist -> scan1 -> scan2b -> perm; join.
// ---------------------------------------------------------------------------
extern "C" void kernel_launch(void* const* d_in, const int* in_sizes, int n_in,
                              void* d_out, int out_size)
{
    const float* feat = (const float*)d_in[0];
    const float* att  = (const float*)d_in[1];
    const int*   src  = (const int*)  d_in[2];
    const int*   dst  = (const int*)  d_in[3];
    const float* W    = (const float*)d_in[4];
    const float* bias = (const float*)d_in[5];
    float*       out  = (float*)d_out;

    int n_nodes = in_sizes[0] / IN_FEAT;
    int n_edges = in_sizes[2];

    __half2* h16;
    cudaGetSymbolAddress((void**)&h16, g_h16);

    cudaFuncSetAttribute(gemm_kernel,
                         cudaFuncAttributeMaxDynamicSharedMemorySize, GEMM_SMEM);

    cudaStream_t side;
    cudaStreamCreateWithFlags(&side, cudaStreamNonBlocking);
    cudaEvent_t evFork, evJoin;
    cudaEventCreateWithFlags(&evFork, cudaEventDisableTiming);
    cudaEventCreateWithFlags(&evJoin, cudaEventDisableTiming);

    // fork: gemm on side stream
    cudaEventRecord(evFork, 0);
    cudaStreamWaitEvent(side, evFork, 0);
    gemm_kernel<<<(n_nodes + 127) / 128, 256, GEMM_SMEM, side>>>(feat, W, bias, h16, n_nodes);
    cudaEventRecord(evJoin, side);

    // binning chain on main stream
    int vthreads = (n_edges + 3) / 4;
    hist_kernel<<<(vthreads + 255) / 256, 256>>>(dst, n_edges);
    scan1_kernel<<<(n_nodes + 255) / 256, 256>>>(n_nodes);
    scan2b_kernel<<<(n_nodes + 255) / 256, 256>>>(n_nodes, n_edges);
    perm_kernel<<<(vthreads + 255) / 256, 256>>>(src, dst, att, n_edges);

    // join, then accumulate
    cudaStreamWaitEvent(0, evJoin, 0);
    long long work = (long long)n_nodes * 32;
    accum_kernel<<<(int)((work + 255) / 256), 256>>>(h16, out, n_nodes);
}